// round 1
// baseline (speedup 1.0000x reference)
#include <cuda_runtime.h>
#include <cstdint>

#define NTOK 4096
#define C_DIM 3072
#define F_DIM 12288
#define NB 32
#define BM_ 128
#define MBM_ 16
#define MBS 256
#define KSEL 1536
#define BKK 16

// ---------------- scratch (device globals; no allocations allowed) ----------------
__device__ float g_bmx[MBS * C_DIM];          // 3 MB   block-mean x
__device__ float g_bmfc1[MBS * F_DIM];        // 12.6MB block-mean fc1 output
__device__ float g_mdiff[NB * F_DIM];         // 1.5 MB per-block channel scores
__device__ int   g_inds[NB * KSEL];           // selected channel ids per block
__device__ float g_delta[(size_t)NB * BM_ * KSEL]; // 25 MB delta activations

// ---------------- kernel 1: block means over 16 tokens ----------------
__global__ void k_bmean(const float* __restrict__ x) {
    int mb = blockIdx.x;
    int c  = blockIdx.y * 512 + threadIdx.x;
    const float* p = x + (size_t)mb * MBM_ * C_DIM + c;
    float s = 0.f;
#pragma unroll
    for (int t = 0; t < MBM_; t++) s += p[(size_t)t * C_DIM];
    g_bmx[mb * C_DIM + c] = s * (1.f / 16.f);
}

// ---------------- kernel 2: bmfc1 = bm_x @ fc1w^T + fc1b (fp32 SGEMM) ----------------
// M=256, N=12288, K=3072. Tile 128x128, BK=16, 256 threads, 8x8 per thread.
__global__ __launch_bounds__(256) void k_gemm_sel(const float* __restrict__ fc1w,
                                                  const float* __restrict__ fc1b) {
    __shared__ float As[BKK][128];
    __shared__ float Bs[BKK][128];
    const int m0 = blockIdx.y * 128, n0 = blockIdx.x * 128;
    const int tid = threadIdx.x;
    const int lr = tid >> 2, lc = tid & 3;
    const int tx = tid & 15, ty = tid >> 4;
    float acc[8][8];
#pragma unroll
    for (int i = 0; i < 8; i++)
#pragma unroll
        for (int j = 0; j < 8; j++) acc[i][j] = 0.f;

    for (int k0 = 0; k0 < C_DIM; k0 += BKK) {
#pragma unroll
        for (int r = 0; r < 2; r++) {
            int row = lr + 64 * r;
            float4 v = *(const float4*)(g_bmx + (size_t)(m0 + row) * C_DIM + k0 + lc * 4);
            As[lc * 4 + 0][row] = v.x; As[lc * 4 + 1][row] = v.y;
            As[lc * 4 + 2][row] = v.z; As[lc * 4 + 3][row] = v.w;
        }
#pragma unroll
        for (int r = 0; r < 2; r++) {
            int row = lr + 64 * r;
            float4 v = *(const float4*)(fc1w + (size_t)(n0 + row) * C_DIM + k0 + lc * 4);
            Bs[lc * 4 + 0][row] = v.x; Bs[lc * 4 + 1][row] = v.y;
            Bs[lc * 4 + 2][row] = v.z; Bs[lc * 4 + 3][row] = v.w;
        }
        __syncthreads();
#pragma unroll
        for (int kk = 0; kk < BKK; kk++) {
            float a[8], b[8];
            *(float4*)&a[0] = *(const float4*)&As[kk][ty * 8];
            *(float4*)&a[4] = *(const float4*)&As[kk][ty * 8 + 4];
            *(float4*)&b[0] = *(const float4*)&Bs[kk][tx * 8];
            *(float4*)&b[4] = *(const float4*)&Bs[kk][tx * 8 + 4];
#pragma unroll
            for (int i = 0; i < 8; i++)
#pragma unroll
                for (int j = 0; j < 8; j++) acc[i][j] = fmaf(a[i], b[j], acc[i][j]);
        }
        __syncthreads();
    }
#pragma unroll
    for (int i = 0; i < 8; i++) {
        int m = m0 + ty * 8 + i;
        float* cp = g_bmfc1 + (size_t)m * F_DIM + n0 + tx * 8;
        const float* bp = fc1b + n0 + tx * 8;
        float4 b0 = *(const float4*)bp, b1 = *(const float4*)(bp + 4);
        float4 o0, o1;
        o0.x = acc[i][0] + b0.x; o0.y = acc[i][1] + b0.y;
        o0.z = acc[i][2] + b0.z; o0.w = acc[i][3] + b0.w;
        o1.x = acc[i][4] + b1.x; o1.y = acc[i][5] + b1.y;
        o1.z = acc[i][6] + b1.z; o1.w = acc[i][7] + b1.w;
        *(float4*)cp = o0; *(float4*)(cp + 4) = o1;
    }
}

// ---------------- kernel 3: mdiff[b][f] = sum_r |bmfc1[8b+r][f] - cache[8b+r][f]| ----------------
__global__ void k_mdiff(const float* __restrict__ cache) {
    int b = blockIdx.y;
    int f = blockIdx.x * 256 + threadIdx.x;
    float s = 0.f;
#pragma unroll
    for (int r = 0; r < 8; r++) {
        size_t idx = (size_t)(b * 8 + r) * F_DIM + f;
        s += fabsf(g_bmfc1[idx] - cache[idx]);
    }
    g_mdiff[b * F_DIM + f] = s;
}

// ---------------- kernel 4: per-block top-1536 via 8-bit radix select ----------------
// mdiff >= 0 so uint bit order == float order. Ties taken lowest-index-first
// (matches jax.lax.top_k set semantics; output is permutation-invariant in k).
__global__ void k_topk() {
    int b = blockIdx.x, tid = threadIdx.x;
    const float* v = g_mdiff + (size_t)b * F_DIM;
    __shared__ int hist[256];
    __shared__ unsigned pref_s;
    __shared__ int rem_s;
    unsigned pref = 0;
    int rem = KSEL;
    for (int pass = 0; pass < 4; pass++) {
        hist[tid] = 0;
        __syncthreads();
        int sh = 24 - 8 * pass;
        for (int f = tid; f < F_DIM; f += 256) {
            unsigned u = __float_as_uint(v[f]);
            bool cand = (pass == 0) || ((u >> (sh + 8)) == pref);
            if (cand) atomicAdd(&hist[(u >> sh) & 255], 1);
        }
        __syncthreads();
        if (tid == 0) {
            int r = rem, bin = 0;
            for (int i = 255; i >= 0; i--) {
                if (r <= hist[i]) { bin = i; break; }
                r -= hist[i];
            }
            pref_s = (pref << 8) | (unsigned)bin;
            rem_s = r;
        }
        __syncthreads();
        pref = pref_s; rem = rem_s;
        __syncthreads();
    }
    // deterministic ordered compaction: thread t owns f in [t*48, t*48+48)
    __shared__ int cnts[256];
    __shared__ int total_s;
    const int f0 = tid * 48, f1 = f0 + 48;
    int c = 0;
    for (int f = f0; f < f1; f++)
        if (__float_as_uint(v[f]) > pref) c++;
    cnts[tid] = c;
    __syncthreads();
    if (tid == 0) {
        int s = 0;
        for (int i = 0; i < 256; i++) { int t = cnts[i]; cnts[i] = s; s += t; }
        total_s = s;
    }
    __syncthreads();
    int pos = cnts[tid];
    for (int f = f0; f < f1; f++)
        if (__float_as_uint(v[f]) > pref) g_inds[b * KSEL + (pos++)] = f;
    if (tid == 0) {
        int base = total_s, need = KSEL - total_s, got = 0;
        for (int f = 0; f < F_DIM && got < need; f++)
            if (__float_as_uint(v[f]) == pref) { g_inds[b * KSEL + base + got] = f; got++; }
    }
}

// ---------------- kernel 5: gathered fc1 GEMM + gelu + delta ----------------
// per block: mid = x_blk(128x3072) @ fc1w[inds]^T + b ; delta = gelu(mid) - cached
__global__ __launch_bounds__(256) void k_gemm1(const float* __restrict__ x,
                                               const float* __restrict__ fc1w,
                                               const float* __restrict__ fc1b,
                                               const float* __restrict__ sAT) {
    __shared__ float As[BKK][128];
    __shared__ float Bs[BKK][128];
    __shared__ int ridx[128];
    __shared__ float bsh[128];
    const int blk = blockIdx.y, n0 = blockIdx.x * 128;
    const int tid = threadIdx.x;
    if (tid < 128) {
        int id = g_inds[blk * KSEL + n0 + tid];
        ridx[tid] = id;
        bsh[tid] = fc1b[id];
    }
    __syncthreads();
    const int lr = tid >> 2, lc = tid & 3;
    const int tx = tid & 15, ty = tid >> 4;
    const float* Ab = x + (size_t)blk * BM_ * C_DIM;
    float acc[8][8];
#pragma unroll
    for (int i = 0; i < 8; i++)
#pragma unroll
        for (int j = 0; j < 8; j++) acc[i][j] = 0.f;

    for (int k0 = 0; k0 < C_DIM; k0 += BKK) {
#pragma unroll
        for (int r = 0; r < 2; r++) {
            int row = lr + 64 * r;
            float4 v = *(const float4*)(Ab + (size_t)row * C_DIM + k0 + lc * 4);
            As[lc * 4 + 0][row] = v.x; As[lc * 4 + 1][row] = v.y;
            As[lc * 4 + 2][row] = v.z; As[lc * 4 + 3][row] = v.w;
        }
#pragma unroll
        for (int r = 0; r < 2; r++) {
            int row = lr + 64 * r;
            const float* wp = fc1w + (size_t)ridx[row] * C_DIM;
            float4 v = *(const float4*)(wp + k0 + lc * 4);
            Bs[lc * 4 + 0][row] = v.x; Bs[lc * 4 + 1][row] = v.y;
            Bs[lc * 4 + 2][row] = v.z; Bs[lc * 4 + 3][row] = v.w;
        }
        __syncthreads();
#pragma unroll
        for (int kk = 0; kk < BKK; kk++) {
            float a[8], b[8];
            *(float4*)&a[0] = *(const float4*)&As[kk][ty * 8];
            *(float4*)&a[4] = *(const float4*)&As[kk][ty * 8 + 4];
            *(float4*)&b[0] = *(const float4*)&Bs[kk][tx * 8];
            *(float4*)&b[4] = *(const float4*)&Bs[kk][tx * 8 + 4];
#pragma unroll
            for (int i = 0; i < 8; i++)
#pragma unroll
                for (int j = 0; j < 8; j++) acc[i][j] = fmaf(a[i], b[j], acc[i][j]);
        }
        __syncthreads();
    }
#pragma unroll
    for (int i = 0; i < 8; i++) {
        int t = ty * 8 + i;
        float outv[8];
#pragma unroll
        for (int j = 0; j < 8; j++) {
            int col = tx * 8 + j;
            float vm = acc[i][j] + bsh[col];
            float g = 0.5f * vm * (1.f + tanhf(0.7978845608028654f * (vm + 0.044715f * vm * vm * vm)));
            float cached = sAT[(size_t)ridx[col] * NTOK + blk * BM_ + t];
            outv[j] = g - cached;
        }
        float* dp = g_delta + ((size_t)blk * BM_ + t) * KSEL + n0 + tx * 8;
        *(float4*)dp = *(float4*)&outv[0];
        *(float4*)(dp + 4) = *(float4*)&outv[4];
    }
}

// ---------------- kernel 6: gathered fc2 GEMM + out_cache add ----------------
// out[blk*128+t][c] = out_cache[...] + sum_j delta[blk][t][j] * fc2w_T[inds[blk][j]][c]
__global__ __launch_bounds__(256) void k_gemm2(const float* __restrict__ fc2wT,
                                               const float* __restrict__ out_cache,
                                               float* __restrict__ out) {
    __shared__ float As[BKK][128];
    __shared__ float Bs[BKK][128];
    __shared__ int kidx[KSEL];
    const int blk = blockIdx.y, n0 = blockIdx.x * 128;
    const int tid = threadIdx.x;
    for (int i = tid; i < KSEL; i += 256) kidx[i] = g_inds[blk * KSEL + i];
    __syncthreads();
    const int lr = tid >> 2, lc = tid & 3;
    const int tx = tid & 15, ty = tid >> 4;
    const float* Ab = g_delta + (size_t)blk * BM_ * KSEL;
    float acc[8][8];
#pragma unroll
    for (int i = 0; i < 8; i++)
#pragma unroll
        for (int j = 0; j < 8; j++) acc[i][j] = 0.f;

    for (int k0 = 0; k0 < KSEL; k0 += BKK) {
#pragma unroll
        for (int r = 0; r < 2; r++) {
            int row = lr + 64 * r;
            float4 v = *(const float4*)(Ab + (size_t)row * KSEL + k0 + lc * 4);
            As[lc * 4 + 0][row] = v.x; As[lc * 4 + 1][row] = v.y;
            As[lc * 4 + 2][row] = v.z; As[lc * 4 + 3][row] = v.w;
        }
#pragma unroll
        for (int r = 0; r < 2; r++) {
            int idx = tid + 256 * r;
            int krow = idx >> 5, c4 = idx & 31;
            const float* wp = fc2wT + (size_t)kidx[k0 + krow] * C_DIM;
            *(float4*)&Bs[krow][c4 * 4] = *(const float4*)(wp + n0 + c4 * 4);
        }
        __syncthreads();
#pragma unroll
        for (int kk = 0; kk < BKK; kk++) {
            float a[8], b[8];
            *(float4*)&a[0] = *(const float4*)&As[kk][ty * 8];
            *(float4*)&a[4] = *(const float4*)&As[kk][ty * 8 + 4];
            *(float4*)&b[0] = *(const float4*)&Bs[kk][tx * 8];
            *(float4*)&b[4] = *(const float4*)&Bs[kk][tx * 8 + 4];
#pragma unroll
            for (int i = 0; i < 8; i++)
#pragma unroll
                for (int j = 0; j < 8; j++) acc[i][j] = fmaf(a[i], b[j], acc[i][j]);
        }
        __syncthreads();
    }
#pragma unroll
    for (int i = 0; i < 8; i++) {
        int row = blk * BM_ + ty * 8 + i;
        const float* ocp = out_cache + (size_t)row * C_DIM + n0 + tx * 8;
        float* op = out + (size_t)row * C_DIM + n0 + tx * 8;
        float4 o0 = *(const float4*)ocp, o1 = *(const float4*)(ocp + 4);
        o0.x += acc[i][0]; o0.y += acc[i][1]; o0.z += acc[i][2]; o0.w += acc[i][3];
        o1.x += acc[i][4]; o1.y += acc[i][5]; o1.z += acc[i][6]; o1.w += acc[i][7];
        *(float4*)op = o0; *(float4*)(op + 4) = o1;
    }
}

// ---------------- launch ----------------
extern "C" void kernel_launch(void* const* d_in, const int* in_sizes, int n_in,
                              void* d_out, int out_size) {
    const float* x     = (const float*)d_in[0];
    const float* fc1w  = (const float*)d_in[1];
    const float* fc1b  = (const float*)d_in[2];
    const float* fc2wT = (const float*)d_in[3];
    const float* bmc   = (const float*)d_in[4];
    const float* sAT   = (const float*)d_in[5];
    const float* outc  = (const float*)d_in[6];
    float* out = (float*)d_out;

    k_bmean<<<dim3(256, 6), 512>>>(x);
    k_gemm_sel<<<dim3(96, 2), 256>>>(fc1w, fc1b);
    k_mdiff<<<dim3(48, 32), 256>>>(bmc);
    k_topk<<<32, 256>>>();
    k_gemm1<<<dim3(12, 32), 256>>>(x, fc1w, fc1b, sAT);
    k_gemm2<<<dim3(24, 32), 256>>>(fc2wT, outc, out);
}

// round 2
// speedup vs baseline: 3.4882x; 3.4882x over previous
#include <cuda_runtime.h>
#include <cstdint>

#define NTOK 4096
#define C_DIM 3072
#define F_DIM 12288
#define NB 32
#define BM_ 128
#define MBM_ 16
#define MBS 256
#define KSEL 1536

// ---------------- scratch ----------------
__device__ float g_bmx[MBS * C_DIM];
__device__ float g_bmfc1[MBS * F_DIM];
__device__ float g_mdiff[NB * F_DIM];
__device__ int   g_inds[NB * KSEL];
__device__ float g_delta[(size_t)NB * KSEL * BM_];  // [blk][ch][token]  (transposed!)

// ---------------- helpers ----------------
__device__ __forceinline__ uint32_t f2tf(float x) {
    uint32_t u;
    asm("cvt.rna.tf32.f32 %0, %1;" : "=r"(u) : "f"(x));
    return u;
}
__device__ __forceinline__ void mma_tf32(float c[4], const uint32_t a[4], const uint32_t b[2]) {
    asm volatile(
        "mma.sync.aligned.m16n8k8.row.col.f32.tf32.tf32.f32 "
        "{%0,%1,%2,%3},{%4,%5,%6,%7},{%8,%9},{%0,%1,%2,%3};"
        : "+f"(c[0]), "+f"(c[1]), "+f"(c[2]), "+f"(c[3])
        : "r"(a[0]), "r"(a[1]), "r"(a[2]), "r"(a[3]), "r"(b[0]), "r"(b[1]));
}
__device__ __forceinline__ float gelu_t(float v) {
    return 0.5f * v * (1.f + tanhf(0.7978845608028654f * (v + 0.044715f * v * v * v)));
}

// ---------------- kernel 1: block means ----------------
__global__ void k_bmean(const float* __restrict__ x) {
    int mb = blockIdx.x;
    int c  = blockIdx.y * 512 + threadIdx.x;
    const float* p = x + (size_t)mb * MBM_ * C_DIM + c;
    float s = 0.f;
#pragma unroll
    for (int t = 0; t < MBM_; t++) s += p[(size_t)t * C_DIM];
    g_bmx[mb * C_DIM + c] = s * (1.f / 16.f);
}

// ---------------- kernel 2: selection GEMM, 3xTF32 (fp32-accurate) ----------------
// C[m=256][n=12288] = bm_x @ fc1w^T + b, K=3072. Tile 128x128, BK=16.
#define SEL_ST 20
__global__ __launch_bounds__(256) void k_gemm_sel(const float* __restrict__ fc1w,
                                                  const float* __restrict__ fc1b) {
    __shared__ uint32_t Ah[128 * SEL_ST], Al[128 * SEL_ST];
    __shared__ uint32_t Bh[128 * SEL_ST], Bl[128 * SEL_ST];
    const int m0 = blockIdx.y * 128, n0 = blockIdx.x * 128;
    const int tid = threadIdx.x, wid = tid >> 5, lane = tid & 31;
    const int wm = wid & 1, wn = wid >> 1;       // warp tile 64x32
    const int grp = lane >> 2, tig = lane & 3;

    float acc[4][4][4];
#pragma unroll
    for (int i = 0; i < 4; i++)
#pragma unroll
        for (int j = 0; j < 4; j++)
#pragma unroll
            for (int q = 0; q < 4; q++) acc[i][j][q] = 0.f;

    float4 ra[2], rb[2];
    const int lrow = tid >> 2, lc4 = tid & 3;
#pragma unroll
    for (int r = 0; r < 2; r++) {
        int row = lrow + 64 * r;
        ra[r] = *(const float4*)(g_bmx + (size_t)(m0 + row) * C_DIM + lc4 * 4);
        rb[r] = *(const float4*)(fc1w + (size_t)(n0 + row) * C_DIM + lc4 * 4);
    }

    for (int k0 = 0; k0 < C_DIM; k0 += 16) {
#pragma unroll
        for (int r = 0; r < 2; r++) {
            int row = lrow + 64 * r;
            int base = row * SEL_ST + lc4 * 4;
            float av[4] = {ra[r].x, ra[r].y, ra[r].z, ra[r].w};
            float bv[4] = {rb[r].x, rb[r].y, rb[r].z, rb[r].w};
#pragma unroll
            for (int i = 0; i < 4; i++) {
                uint32_t h = f2tf(av[i]);
                Ah[base + i] = h;
                Al[base + i] = f2tf(av[i] - __uint_as_float(h));
                h = f2tf(bv[i]);
                Bh[base + i] = h;
                Bl[base + i] = f2tf(bv[i] - __uint_as_float(h));
            }
        }
        __syncthreads();
        if (k0 + 16 < C_DIM) {
#pragma unroll
            for (int r = 0; r < 2; r++) {
                int row = lrow + 64 * r;
                ra[r] = *(const float4*)(g_bmx + (size_t)(m0 + row) * C_DIM + k0 + 16 + lc4 * 4);
                rb[r] = *(const float4*)(fc1w + (size_t)(n0 + row) * C_DIM + k0 + 16 + lc4 * 4);
            }
        }
#pragma unroll
        for (int ks = 0; ks < 2; ks++) {
            const int kk = ks * 8;
            uint32_t ah[4][4], al[4][4], bh[4][2], bl[4][2];
#pragma unroll
            for (int mt = 0; mt < 4; mt++) {
                int mr = wm * 64 + mt * 16 + grp;
                ah[mt][0] = Ah[mr * SEL_ST + kk + tig];
                ah[mt][1] = Ah[(mr + 8) * SEL_ST + kk + tig];
                ah[mt][2] = Ah[mr * SEL_ST + kk + tig + 4];
                ah[mt][3] = Ah[(mr + 8) * SEL_ST + kk + tig + 4];
                al[mt][0] = Al[mr * SEL_ST + kk + tig];
                al[mt][1] = Al[(mr + 8) * SEL_ST + kk + tig];
                al[mt][2] = Al[mr * SEL_ST + kk + tig + 4];
                al[mt][3] = Al[(mr + 8) * SEL_ST + kk + tig + 4];
            }
#pragma unroll
            for (int nt = 0; nt < 4; nt++) {
                int nb = wn * 32 + nt * 8 + grp;
                bh[nt][0] = Bh[nb * SEL_ST + kk + tig];
                bh[nt][1] = Bh[nb * SEL_ST + kk + tig + 4];
                bl[nt][0] = Bl[nb * SEL_ST + kk + tig];
                bl[nt][1] = Bl[nb * SEL_ST + kk + tig + 4];
            }
#pragma unroll
            for (int mt = 0; mt < 4; mt++)
#pragma unroll
                for (int nt = 0; nt < 4; nt++) {
                    mma_tf32(acc[mt][nt], ah[mt], bl[nt]);
                    mma_tf32(acc[mt][nt], al[mt], bh[nt]);
                    mma_tf32(acc[mt][nt], ah[mt], bh[nt]);
                }
        }
        __syncthreads();
    }
#pragma unroll
    for (int mt = 0; mt < 4; mt++)
#pragma unroll
        for (int nt = 0; nt < 4; nt++) {
            int row = m0 + wm * 64 + mt * 16 + grp;
            int col = n0 + wn * 32 + nt * 8 + tig * 2;
            float b0 = fc1b[col], b1 = fc1b[col + 1];
            float2 o;
            o.x = acc[mt][nt][0] + b0; o.y = acc[mt][nt][1] + b1;
            *(float2*)(g_bmfc1 + (size_t)row * F_DIM + col) = o;
            o.x = acc[mt][nt][2] + b0; o.y = acc[mt][nt][3] + b1;
            *(float2*)(g_bmfc1 + (size_t)(row + 8) * F_DIM + col) = o;
        }
}

// ---------------- kernel 3: mdiff ----------------
__global__ void k_mdiff(const float* __restrict__ cache) {
    int b = blockIdx.y;
    int f = blockIdx.x * 256 + threadIdx.x;
    float s = 0.f;
#pragma unroll
    for (int r = 0; r < 8; r++) {
        size_t idx = (size_t)(b * 8 + r) * F_DIM + f;
        s += fabsf(g_bmfc1[idx] - cache[idx]);
    }
    g_mdiff[b * F_DIM + f] = s;
}

// ---------------- kernel 4: parallel top-1536 (radix select, 1024 threads) ----------------
__global__ __launch_bounds__(1024) void k_topk() {
    const int b = blockIdx.x, tid = threadIdx.x;
    const int lane = tid & 31, w = tid >> 5;
    const float* v = g_mdiff + (size_t)b * F_DIM;
    const int f0 = tid * 12;
    float vals[12];
#pragma unroll
    for (int j = 0; j < 12; j++) vals[j] = v[f0 + j];

    __shared__ int hist[256];
    __shared__ unsigned pref_s;
    __shared__ int rem_s;
    __shared__ int wsum[32];
    __shared__ int total_s;

    unsigned pref = 0;
    int rem = KSEL;
    for (int pass = 0; pass < 4; pass++) {
        const int sh = 24 - 8 * pass;
        if (tid < 256) hist[tid] = 0;
        __syncthreads();
#pragma unroll
        for (int j = 0; j < 12; j++) {
            unsigned u = __float_as_uint(vals[j]);
            if (pass == 0 || (u >> (sh + 8)) == pref)
                atomicAdd(&hist[(u >> sh) & 255], 1);
        }
        __syncthreads();
        // suffix sums over hist (Hillis-Steele)
        for (int off = 1; off < 256; off <<= 1) {
            int x_;
            if (tid < 256) x_ = hist[tid] + ((tid + off < 256) ? hist[tid + off] : 0);
            __syncthreads();
            if (tid < 256) hist[tid] = x_;
            __syncthreads();
        }
        if (tid < 256) {
            int nxt = (tid == 255) ? 0 : hist[tid + 1];
            if (hist[tid] >= rem && nxt < rem) {
                pref_s = (pref << 8) | (unsigned)tid;
                rem_s = rem - nxt;
            }
        }
        __syncthreads();
        pref = pref_s;
        rem = rem_s;
        __syncthreads();
    }

    // counts
    int cgt = 0, ceq = 0;
#pragma unroll
    for (int j = 0; j < 12; j++) {
        unsigned u = __float_as_uint(vals[j]);
        if (u > pref) cgt++;
        else if (u == pref) ceq++;
    }
    // exclusive scan of cgt
    int inc = cgt;
#pragma unroll
    for (int off = 1; off < 32; off <<= 1) {
        int n_ = __shfl_up_sync(0xffffffffu, inc, off);
        if (lane >= off) inc += n_;
    }
    if (lane == 31) wsum[w] = inc;
    __syncthreads();
    if (w == 0) {
        int t = wsum[lane];
#pragma unroll
        for (int off = 1; off < 32; off <<= 1) {
            int n_ = __shfl_up_sync(0xffffffffu, t, off);
            if (lane >= off) t += n_;
        }
        wsum[lane] = t;
    }
    __syncthreads();
    int base = (w > 0 ? wsum[w - 1] : 0) + inc - cgt;
    if (tid == 1023) total_s = base + cgt;
    __syncthreads();
    const int total_gt = total_s;
    {
        int pos = base;
#pragma unroll
        for (int j = 0; j < 12; j++)
            if (__float_as_uint(vals[j]) > pref) g_inds[b * KSEL + (pos++)] = f0 + j;
    }
    __syncthreads();
    // exclusive scan of ceq
    inc = ceq;
#pragma unroll
    for (int off = 1; off < 32; off <<= 1) {
        int n_ = __shfl_up_sync(0xffffffffu, inc, off);
        if (lane >= off) inc += n_;
    }
    if (lane == 31) wsum[w] = inc;
    __syncthreads();
    if (w == 0) {
        int t = wsum[lane];
#pragma unroll
        for (int off = 1; off < 32; off <<= 1) {
            int n_ = __shfl_up_sync(0xffffffffu, t, off);
            if (lane >= off) t += n_;
        }
        wsum[lane] = t;
    }
    __syncthreads();
    int ebase = (w > 0 ? wsum[w - 1] : 0) + inc - ceq;
    const int need = KSEL - total_gt;
#pragma unroll
    for (int j = 0; j < 12; j++)
        if (__float_as_uint(vals[j]) == pref) {
            if (ebase < need) g_inds[b * KSEL + total_gt + ebase] = f0 + j;
            ebase++;
        }
}

// ---------------- kernel 5: gathered fc1 GEMM (tf32) + gelu + delta (transposed out) ----------
// C[m=ch(128)][n=token(128)] = fc1w[inds] @ x_blk^T; K=3072, BK=32.
#define G1_ST 36
__global__ __launch_bounds__(256) void k_gemm1(const float* __restrict__ x,
                                               const float* __restrict__ fc1w,
                                               const float* __restrict__ fc1b,
                                               const float* __restrict__ sAT) {
    __shared__ uint32_t As[128 * G1_ST];   // gathered w1, m(ch)-major
    __shared__ uint32_t Bs[128 * G1_ST];   // x tile, n(token)-major
    __shared__ int ridx[128];
    __shared__ float bsh[128];
    const int blk = blockIdx.y, mchunk = blockIdx.x;
    const int tid = threadIdx.x, wid = tid >> 5, lane = tid & 31;
    const int wm = wid & 1, wn = wid >> 1;
    const int grp = lane >> 2, tig = lane & 3;

    if (tid < 128) {
        int id = g_inds[blk * KSEL + mchunk * 128 + tid];
        ridx[tid] = id;
        bsh[tid] = fc1b[id];
    }
    __syncthreads();

    float acc[4][4][4];
#pragma unroll
    for (int i = 0; i < 4; i++)
#pragma unroll
        for (int j = 0; j < 4; j++)
#pragma unroll
            for (int q = 0; q < 4; q++) acc[i][j][q] = 0.f;

    const float* xb = x + (size_t)blk * BM_ * C_DIM;
    const int lrow = tid >> 3, lc4 = tid & 7;
    float4 ra[4], rb[4];
#pragma unroll
    for (int r = 0; r < 4; r++) {
        int row = lrow + 32 * r;
        ra[r] = *(const float4*)(fc1w + (size_t)ridx[row] * C_DIM + lc4 * 4);
        rb[r] = *(const float4*)(xb + (size_t)row * C_DIM + lc4 * 4);
    }

    for (int k0 = 0; k0 < C_DIM; k0 += 32) {
#pragma unroll
        for (int r = 0; r < 4; r++) {
            int row = lrow + 32 * r;
            int base = row * G1_ST + lc4 * 4;
            As[base + 0] = f2tf(ra[r].x); As[base + 1] = f2tf(ra[r].y);
            As[base + 2] = f2tf(ra[r].z); As[base + 3] = f2tf(ra[r].w);
            Bs[base + 0] = f2tf(rb[r].x); Bs[base + 1] = f2tf(rb[r].y);
            Bs[base + 2] = f2tf(rb[r].z); Bs[base + 3] = f2tf(rb[r].w);
        }
        __syncthreads();
        if (k0 + 32 < C_DIM) {
#pragma unroll
            for (int r = 0; r < 4; r++) {
                int row = lrow + 32 * r;
                ra[r] = *(const float4*)(fc1w + (size_t)ridx[row] * C_DIM + k0 + 32 + lc4 * 4);
                rb[r] = *(const float4*)(xb + (size_t)row * C_DIM + k0 + 32 + lc4 * 4);
            }
        }
#pragma unroll
        for (int ks = 0; ks < 4; ks++) {
            const int kk = ks * 8;
            uint32_t af[4][4], bf[4][2];
#pragma unroll
            for (int mt = 0; mt < 4; mt++) {
                int mr = wm * 64 + mt * 16 + grp;
                af[mt][0] = As[mr * G1_ST + kk + tig];
                af[mt][1] = As[(mr + 8) * G1_ST + kk + tig];
                af[mt][2] = As[mr * G1_ST + kk + tig + 4];
                af[mt][3] = As[(mr + 8) * G1_ST + kk + tig + 4];
            }
#pragma unroll
            for (int nt = 0; nt < 4; nt++) {
                int nb = wn * 32 + nt * 8 + grp;
                bf[nt][0] = Bs[nb * G1_ST + kk + tig];
                bf[nt][1] = Bs[nb * G1_ST + kk + tig + 4];
            }
#pragma unroll
            for (int mt = 0; mt < 4; mt++)
#pragma unroll
                for (int nt = 0; nt < 4; nt++) mma_tf32(acc[mt][nt], af[mt], bf[nt]);
        }
        __syncthreads();
    }

    // epilogue: gelu(acc + b) - cached -> g_delta[blk][ch][token]
#pragma unroll
    for (int mt = 0; mt < 4; mt++)
#pragma unroll
        for (int nt = 0; nt < 4; nt++) {
            int t0 = wn * 32 + nt * 8 + tig * 2;
#pragma unroll
            for (int half = 0; half < 2; half++) {
                int r = wm * 64 + mt * 16 + grp + 8 * half;
                float bb = bsh[r];
                int chg = ridx[r];
                const float* cp = sAT + (size_t)chg * NTOK + blk * BM_ + t0;
                float2 cached = *(const float2*)cp;
                float v0 = acc[mt][nt][half * 2 + 0] + bb;
                float v1 = acc[mt][nt][half * 2 + 1] + bb;
                float2 o;
                o.x = gelu_t(v0) - cached.x;
                o.y = gelu_t(v1) - cached.y;
                *(float2*)(g_delta + ((size_t)blk * KSEL + mchunk * 128 + r) * BM_ + t0) = o;
            }
        }
}

// ---------------- kernel 6: gathered fc2 GEMM (tf32) + out_cache add ----------------
// C[m=token(128)][n=cdim(128)] ; K=1536, A=deltaT k-major, B=gathered fc2wT k-major.
#define G2_ST 136
__global__ __launch_bounds__(256) void k_gemm2(const float* __restrict__ fc2wT,
                                               const float* __restrict__ out_cache,
                                               float* __restrict__ out) {
    __shared__ uint32_t As[32 * G2_ST];
    __shared__ uint32_t Bs[32 * G2_ST];
    __shared__ int kidx[KSEL];
    const int blk = blockIdx.y, n0 = blockIdx.x * 128;
    const int tid = threadIdx.x, wid = tid >> 5, lane = tid & 31;
    const int wm = wid & 1, wn = wid >> 1;
    const int grp = lane >> 2, tig = lane & 3;

    for (int i = tid; i < KSEL; i += 256) kidx[i] = g_inds[blk * KSEL + i];
    __syncthreads();

    float acc[4][4][4];
#pragma unroll
    for (int i = 0; i < 4; i++)
#pragma unroll
        for (int j = 0; j < 4; j++)
#pragma unroll
            for (int q = 0; q < 4; q++) acc[i][j][q] = 0.f;

    const float* Ab = g_delta + (size_t)blk * KSEL * BM_;
    float4 ra[4], rb[4];
#pragma unroll
    for (int r = 0; r < 4; r++) {
        int idx = tid + 256 * r;
        int ch = idx >> 5, t4 = idx & 31;
        ra[r] = *(const float4*)(Ab + (size_t)ch * BM_ + t4 * 4);
        rb[r] = *(const float4*)(fc2wT + (size_t)kidx[ch] * C_DIM + n0 + t4 * 4);
    }

    for (int k0 = 0; k0 < KSEL; k0 += 32) {
#pragma unroll
        for (int r = 0; r < 4; r++) {
            int idx = tid + 256 * r;
            int ch = idx >> 5, t4 = idx & 31;
            int base = ch * G2_ST + t4 * 4;
            As[base + 0] = f2tf(ra[r].x); As[base + 1] = f2tf(ra[r].y);
            As[base + 2] = f2tf(ra[r].z); As[base + 3] = f2tf(ra[r].w);
            Bs[base + 0] = f2tf(rb[r].x); Bs[base + 1] = f2tf(rb[r].y);
            Bs[base + 2] = f2tf(rb[r].z); Bs[base + 3] = f2tf(rb[r].w);
        }
        __syncthreads();
        if (k0 + 32 < KSEL) {
#pragma unroll
            for (int r = 0; r < 4; r++) {
                int idx = tid + 256 * r;
                int ch = idx >> 5, t4 = idx & 31;
                ra[r] = *(const float4*)(Ab + (size_t)(k0 + 32 + ch) * BM_ + t4 * 4);
                rb[r] = *(const float4*)(fc2wT + (size_t)kidx[k0 + 32 + ch] * C_DIM + n0 + t4 * 4);
            }
        }
#pragma unroll
        for (int ks = 0; ks < 4; ks++) {
            const int kk = ks * 8;
            uint32_t af[4][4], bf[4][2];
#pragma unroll
            for (int mt = 0; mt < 4; mt++) {
                int mb = wm * 64 + mt * 16 + grp;
                af[mt][0] = As[(kk + tig) * G2_ST + mb];
                af[mt][1] = As[(kk + tig) * G2_ST + mb + 8];
                af[mt][2] = As[(kk + tig + 4) * G2_ST + mb];
                af[mt][3] = As[(kk + tig + 4) * G2_ST + mb + 8];
            }
#pragma unroll
            for (int nt = 0; nt < 4; nt++) {
                int nb = wn * 32 + nt * 8 + grp;
                bf[nt][0] = Bs[(kk + tig) * G2_ST + nb];
                bf[nt][1] = Bs[(kk + tig + 4) * G2_ST + nb];
            }
#pragma unroll
            for (int mt = 0; mt < 4; mt++)
#pragma unroll
                for (int nt = 0; nt < 4; nt++) mma_tf32(acc[mt][nt], af[mt], bf[nt]);
        }
        __syncthreads();
    }

#pragma unroll
    for (int mt = 0; mt < 4; mt++)
#pragma unroll
        for (int nt = 0; nt < 4; nt++) {
            int col = n0 + wn * 32 + nt * 8 + tig * 2;
#pragma unroll
            for (int half = 0; half < 2; half++) {
                int trow = wm * 64 + mt * 16 + grp + 8 * half;
                size_t off = (size_t)(blk * BM_ + trow) * C_DIM + col;
                float2 oc = *(const float2*)(out_cache + off);
                float2 o;
                o.x = oc.x + acc[mt][nt][half * 2 + 0];
                o.y = oc.y + acc[mt][nt][half * 2 + 1];
                *(float2*)(out + off) = o;
            }
        }
}

// ---------------- launch ----------------
extern "C" void kernel_launch(void* const* d_in, const int* in_sizes, int n_in,
                              void* d_out, int out_size) {
    const float* x     = (const float*)d_in[0];
    const float* fc1w  = (const float*)d_in[1];
    const float* fc1b  = (const float*)d_in[2];
    const float* fc2wT = (const float*)d_in[3];
    const float* bmc   = (const float*)d_in[4];
    const float* sAT   = (const float*)d_in[5];
    const float* outc  = (const float*)d_in[6];
    float* out = (float*)d_out;

    k_bmean<<<dim3(256, 6), 512>>>(x);
    k_gemm_sel<<<dim3(96, 2), 256>>>(fc1w, fc1b);
    k_mdiff<<<dim3(48, 32), 256>>>(bmc);
    k_topk<<<32, 1024>>>();
    k_gemm1<<<dim3(12, 32), 256>>>(x, fc1w, fc1b, sAT);
    k_gemm2<<<dim3(24, 32), 256>>>(fc2wT, outc, out);
}